// round 12
// baseline (speedup 1.0000x reference)
#include <cuda_runtime.h>
#include <cuda_bf16.h>
#include <cstdint>

#define S 1024
#define B 8192
#define EPSF 1e-8f
#define THREADS 256
#define SEG 128              // timesteps per warp segment
#define LPT 4                // timesteps per lane
#define WPR 8                // warps per row
#define GRID 1024            // persistent row blocks
#define RPB (B / GRID)       // 8 rows per block

__device__ float g_ga[S];   // gamma*lam
__device__ float g_gb[S];   // gamma*(1-lam)

__global__ void setup_kernel(const float* __restrict__ raw_gamma,
                             const float* __restrict__ raw_lambd)
{
    const float gamma = fmaxf(tanhf(raw_gamma[0]), EPSF);
    int i = threadIdx.x;
    float lam = fmaxf(tanhf(raw_lambd[i]), EPSF);
    g_ga[i] = gamma * lam;
    g_gb[i] = gamma * (1.0f - lam);
}

__device__ __forceinline__ void cp_async4(void* smem_dst, const void* gmem_src) {
    unsigned int s = (unsigned int)__cvta_generic_to_shared(smem_dst);
    asm volatile("cp.async.ca.shared.global [%0], [%1], 4;" :: "r"(s), "l"(gmem_src));
}
__device__ __forceinline__ void cp_async16(void* smem_dst, const void* gmem_src) {
    unsigned int s = (unsigned int)__cvta_generic_to_shared(smem_dst);
    asm volatile("cp.async.cg.shared.global [%0], [%1], 16;" :: "r"(s), "l"(gmem_src));
}

// Persistent blocks: 8 contiguous rows per block, double-buffered cp.async
// pipeline across rows. 8 warps per row, 128-step segment, 4 steps/lane.
__global__ __launch_bounds__(THREADS, 7)
void td_lambda_kernel(const float* __restrict__ values,
                      const float* __restrict__ rewards,
                      const int*   __restrict__ dones,
                      float* __restrict__ out)
{
    __shared__ float  s_v[2][WPR][SEG + 4];   // padded values
    __shared__ float4 s_r[2][WPR][32];        // rewards (16B cp.async)
    __shared__ int4   s_d[2][WPR][32];        // dones   (16B cp.async)
    __shared__ float  s_cA[2][WPR], s_cB[2][WPR];
    __shared__ float  s_part[THREADS];

    const int tid  = threadIdx.x;
    const int lane = tid & 31;
    const int warp = tid >> 5;

    if (blockIdx.x < GRID) {
        const int seg     = warp;
        const int segbase = seg * SEG;
        const int base    = segbase + lane * LPT;
        const int b0      = blockIdx.x * RPB;

        // tables hoisted: same base for all 8 rows
        const float4 ga4 = *(const float4*)(g_ga + base);
        const float4 gb4 = *(const float4*)(g_gb + base);
        const float ga[LPT] = {ga4.x, ga4.y, ga4.z, ga4.w};
        const float gb[LPT] = {gb4.x, gb4.y, gb4.z, gb4.w};

        // ---- prologue: issue row b0 ----
        {
            const float* vrow = values  + (size_t)b0 * (S + 1);
            const float* rrow = rewards + (size_t)b0 * S;
            const int*   drow = dones   + (size_t)b0 * S;
            #pragma unroll
            for (int k = 0; k < 4; ++k)
                cp_async4(&s_v[0][warp][lane + 33 * k],
                          vrow + segbase + 1 + lane + 32 * k);
            cp_async16(&s_r[0][warp][lane], rrow + base);
            cp_async16(&s_d[0][warp][lane], drow + base);
            asm volatile("cp.async.commit_group;");
        }
        float vS = __ldg(&values[(size_t)b0 * (S + 1) + S]);

        #pragma unroll 2
        for (int i = 0; i < RPB; ++i) {
            const int b   = b0 + i;
            const int buf = i & 1;

            float nvS = 0.0f;
            if (i + 1 < RPB) {
                const int bn = b + 1;
                const float* vrow = values  + (size_t)bn * (S + 1);
                const float* rrow = rewards + (size_t)bn * S;
                const int*   drow = dones   + (size_t)bn * S;
                #pragma unroll
                for (int k = 0; k < 4; ++k)
                    cp_async4(&s_v[buf ^ 1][warp][lane + 33 * k],
                              vrow + segbase + 1 + lane + 32 * k);
                cp_async16(&s_r[buf ^ 1][warp][lane], rrow + base);
                cp_async16(&s_d[buf ^ 1][warp][lane], drow + base);
                asm volatile("cp.async.commit_group;");
                nvS = __ldg(&values[(size_t)bn * (S + 1) + S]);
                asm volatile("cp.async.wait_group 1;");   // current row done
            } else {
                asm volatile("cp.async.wait_group 0;");
            }
            __syncwarp();

            // ---- consume current row from smem ----
            float4 r4 = s_r[buf][warp][lane];
            int4   d4 = s_d[buf][warp][lane];
            const float* vbuf = &s_v[buf][warp][lane * LPT + (lane >> 3)];

            float r[LPT]  = {r4.x, r4.y, r4.z, r4.w};
            int   dn[LPT] = {d4.x, d4.y, d4.z, d4.w};

            float a[LPT], bb[LPT];
            #pragma unroll
            for (int j = 0; j < LPT; ++j) {
                float v = vbuf[j];
                bool  z = (dn[j] != 0);
                a[j]  = z ? 0.0f : ga[j];
                bb[j] = z ? r[j] : fmaf(gb[j], v, r[j]);
            }

            // local composition
            float A = a[LPT - 1], Bc = bb[LPT - 1];
            #pragma unroll
            for (int j = LPT - 2; j >= 0; --j) {
                Bc = fmaf(a[j], Bc, bb[j]);
                A  = a[j] * A;
            }

            // warp suffix scan
            float sA = A, sB = Bc;
            #pragma unroll
            for (int off = 1; off < 32; off <<= 1) {
                float a2 = __shfl_down_sync(0xffffffffu, sA, off);
                float b2 = __shfl_down_sync(0xffffffffu, sB, off);
                if (lane + off < 32) {
                    sB = fmaf(sA, b2, sB);
                    sA = sA * a2;
                }
            }

            if (lane == 0) { s_cA[buf][warp] = sA; s_cB[buf][warp] = sB; }
            __syncthreads();

            // cross-segment entry carry
            float carry = vS;
            #pragma unroll
            for (int k = WPR - 1; k >= 1; --k) {
                if (k > seg)
                    carry = fmaf(s_cA[buf][k], carry, s_cB[buf][k]);
            }

            float eA = __shfl_down_sync(0xffffffffu, sA, 1);
            float eB = __shfl_down_sync(0xffffffffu, sB, 1);
            if (lane == 31) { eA = 1.0f; eB = 0.0f; }
            float x = fmaf(eA, carry, eB);

            float o[LPT];
            #pragma unroll
            for (int j = LPT - 1; j >= 0; --j) {
                x = fmaf(a[j], x, bb[j]);
                o[j] = x;
            }
            __stcs((float4*)(out + (size_t)b * S + base),
                   make_float4(o[0], o[1], o[2], o[3]));

            vS = nvS;
        }
    } else {
        // ---------------- srw (sum_reward_weights) ----------------
        float* s_w = &s_v[0][0][0];   // 2112 contiguous floats >= S

        if (tid < 32) {
            float carry = 1.0f;
            for (int c = S / 32 - 1; c >= 0; --c) {
                const int t = c * 32 + lane;
                float a  = g_ga[t];
                float bb = g_gb[t];
                #pragma unroll
                for (int off = 1; off < 32; off <<= 1) {
                    float a2 = __shfl_down_sync(0xffffffffu, a,  off);
                    float b2 = __shfl_down_sync(0xffffffffu, bb, off);
                    if (lane + off < 32) {
                        bb = fmaf(a, b2, bb);
                        a  = a * a2;
                    }
                }
                float vv = fmaf(a, carry, bb);
                s_w[t] = fmaxf(1.0f - vv, EPSF);
                carry = __shfl_sync(0xffffffffu, vv, 0);
            }
        }
        __syncthreads();

        float ps = 0.0f;
        for (int i = tid; i < S; i += THREADS) ps += s_w[i];
        s_part[tid] = ps;
        __syncthreads();
        for (int stride = THREADS / 2; stride > 0; stride >>= 1) {
            if (tid < stride) s_part[tid] += s_part[tid + stride];
            __syncthreads();
        }
        float mean = s_part[0] * (1.0f / (float)S);
        float inv  = 1.0f / fmaxf(mean, EPSF);
        for (int i = tid; i < S; i += THREADS)
            out[(size_t)B * S + i] = s_w[i] * inv;
    }
}

extern "C" void kernel_launch(void* const* d_in, const int* in_sizes, int n_in,
                              void* d_out, int out_size) {
    const float* raw_gamma = (const float*)d_in[0];
    const float* raw_lambd = (const float*)d_in[1];
    const float* values    = (const float*)d_in[2];
    const float* rewards   = (const float*)d_in[3];
    const int*   dones     = (const int*)d_in[4];
    float* out = (float*)d_out;

    setup_kernel<<<1, S>>>(raw_gamma, raw_lambd);
    td_lambda_kernel<<<GRID + 1, THREADS>>>(values, rewards, dones, out);
}

// round 13
// speedup vs baseline: 1.6186x; 1.6186x over previous
#include <cuda_runtime.h>
#include <cuda_bf16.h>
#include <cstdint>

#define S 1024
#define B 8192
#define EPSF 1e-8f
#define THREADS 256
#define SEG 128              // timesteps per warp segment
#define LPT 4                // timesteps per lane
#define WPR 8                // warps per row
#define NBLK B               // 1 row per block

// accurate-enough tanh: rel err ~1e-7, ~6 instructions
__device__ __forceinline__ float tanh_acc(float x) {
    float e = __expf(2.0f * x);
    return 1.0f - __fdividef(2.0f, e + 1.0f);
}

__device__ __forceinline__ void cp_async4(void* smem_dst, const void* gmem_src) {
    unsigned int s = (unsigned int)__cvta_generic_to_shared(smem_dst);
    asm volatile("cp.async.ca.shared.global [%0], [%1], 4;" :: "r"(s), "l"(gmem_src));
}

// Two-level parallel reverse affine scan: 8 warps per row, 128-step segment
// per warp, 4 timesteps per lane. Tables computed inline (no setup kernel).
__global__ __launch_bounds__(THREADS, 8)
void td_lambda_kernel(const float* __restrict__ raw_gamma,
                      const float* __restrict__ raw_lambd,
                      const float* __restrict__ values,
                      const float* __restrict__ rewards,
                      const int*   __restrict__ dones,
                      float* __restrict__ out)
{
    __shared__ float s_v[WPR][SEG + SEG / 32];   // 8 x 132, padded
    __shared__ float s_cA[WPR], s_cB[WPR];
    __shared__ float s_part[THREADS];            // srw scratch

    const int tid  = threadIdx.x;
    const int lane = tid & 31;
    const int warp = tid >> 5;

    if (blockIdx.x < NBLK) {
        const int b   = blockIdx.x;
        const int seg = warp;                    // 0..7
        const float* __restrict__ rrow = rewards + (size_t)b * S;
        const int*   __restrict__ drow = dones   + (size_t)b * S;
        const float* __restrict__ vrow = values  + (size_t)b * (S + 1);
        float* __restrict__ orow = out + (size_t)b * S;

        const int segbase = seg * SEG;
        const int base    = segbase + lane * LPT;

        // ---- v: gmem -> padded smem via cp.async ----
        #pragma unroll
        for (int k = 0; k < 4; ++k)
            cp_async4(&s_v[warp][lane + 33 * k],
                      vrow + segbase + 1 + lane + 32 * k);
        asm volatile("cp.async.commit_group;");

        // ---- r/d loads while copies fly ----
        float4 r4 = __ldcs((const float4*)(rrow + base));
        int4   d4 = __ldcs((const int4*)(drow + base));
        float4 rl4 = *(const float4*)(raw_lambd + base);
        const float vS = __ldg(&vrow[S]);

        // ---- inline tables: gamma + 4 lambdas per thread ----
        const float gamma = fmaxf(tanh_acc(raw_gamma[0]), EPSF);
        float lam[LPT] = {fmaxf(tanh_acc(rl4.x), EPSF), fmaxf(tanh_acc(rl4.y), EPSF),
                          fmaxf(tanh_acc(rl4.z), EPSF), fmaxf(tanh_acc(rl4.w), EPSF)};
        float ga[LPT], gb[LPT];
        #pragma unroll
        for (int j = 0; j < LPT; ++j) {
            ga[j] = gamma * lam[j];
            gb[j] = gamma * (1.0f - lam[j]);
        }

        asm volatile("cp.async.wait_group 0;");
        __syncwarp();

        float r[LPT]  = {r4.x, r4.y, r4.z, r4.w};
        int   dn[LPT] = {d4.x, d4.y, d4.z, d4.w};
        // conflict-free: bank(4l + l>>3) distinct over lanes
        const float* vbuf = &s_v[warp][lane * LPT + (lane >> 3)];

        float a[LPT], bb[LPT];
        #pragma unroll
        for (int j = 0; j < LPT; ++j) {
            float v = vbuf[j];
            bool  z = (dn[j] != 0);
            a[j]  = z ? 0.0f : ga[j];
            bb[j] = z ? r[j] : fmaf(gb[j], v, r[j]);
        }

        // local composition G = F_j0 ∘ ... ∘ F_j3
        float A = a[LPT - 1], Bc = bb[LPT - 1];
        #pragma unroll
        for (int j = LPT - 2; j >= 0; --j) {
            Bc = fmaf(a[j], Bc, bb[j]);
            A  = a[j] * A;
        }

        // warp suffix scan of lane composites
        float sA = A, sB = Bc;
        #pragma unroll
        for (int off = 1; off < 32; off <<= 1) {
            float a2 = __shfl_down_sync(0xffffffffu, sA, off);
            float b2 = __shfl_down_sync(0xffffffffu, sB, off);
            if (lane + off < 32) {
                sB = fmaf(sA, b2, sB);
                sA = sA * a2;
            }
        }

        if (lane == 0) { s_cA[warp] = sA; s_cB[warp] = sB; }
        __syncthreads();

        // entry carry: apply composites of segments seg+1..7 to v_S
        float carry = vS;
        #pragma unroll
        for (int k = WPR - 1; k >= 1; --k) {
            if (k > seg)
                carry = fmaf(s_cA[k], carry, s_cB[k]);
        }

        float eA = __shfl_down_sync(0xffffffffu, sA, 1);
        float eB = __shfl_down_sync(0xffffffffu, sB, 1);
        if (lane == 31) { eA = 1.0f; eB = 0.0f; }
        float x = fmaf(eA, carry, eB);

        float o[LPT];
        #pragma unroll
        for (int j = LPT - 1; j >= 0; --j) {
            x = fmaf(a[j], x, bb[j]);
            o[j] = x;
        }
        __stcs((float4*)(orow + base), make_float4(o[0], o[1], o[2], o[3]));
    } else {
        // ---------------- srw (sum_reward_weights) ----------------
        float* s_w = &s_v[0][0];   // contiguous floats >= S
        const float gamma = fmaxf(tanh_acc(raw_gamma[0]), EPSF);

        if (tid < 32) {
            float carry = 1.0f;
            for (int c = S / 32 - 1; c >= 0; --c) {
                const int t = c * 32 + lane;
                float lam = fmaxf(tanh_acc(raw_lambd[t]), EPSF);
                float a  = gamma * lam;
                float bb = gamma * (1.0f - lam);
                #pragma unroll
                for (int off = 1; off < 32; off <<= 1) {
                    float a2 = __shfl_down_sync(0xffffffffu, a,  off);
                    float b2 = __shfl_down_sync(0xffffffffu, bb, off);
                    if (lane + off < 32) {
                        bb = fmaf(a, b2, bb);
                        a  = a * a2;
                    }
                }
                float vv = fmaf(a, carry, bb);
                s_w[t] = fmaxf(1.0f - vv, EPSF);
                carry = __shfl_sync(0xffffffffu, vv, 0);
            }
        }
        __syncthreads();

        float ps = 0.0f;
        for (int i = tid; i < S; i += THREADS) ps += s_w[i];
        s_part[tid] = ps;
        __syncthreads();
        for (int stride = THREADS / 2; stride > 0; stride >>= 1) {
            if (tid < stride) s_part[tid] += s_part[tid + stride];
            __syncthreads();
        }
        float mean = s_part[0] * (1.0f / (float)S);
        float inv  = 1.0f / fmaxf(mean, EPSF);
        for (int i = tid; i < S; i += THREADS)
            out[(size_t)B * S + i] = s_w[i] * inv;
    }
}

extern "C" void kernel_launch(void* const* d_in, const int* in_sizes, int n_in,
                              void* d_out, int out_size) {
    const float* raw_gamma = (const float*)d_in[0];
    const float* raw_lambd = (const float*)d_in[1];
    const float* values    = (const float*)d_in[2];
    const float* rewards   = (const float*)d_in[3];
    const int*   dones     = (const int*)d_in[4];
    float* out = (float*)d_out;

    td_lambda_kernel<<<NBLK + 1, THREADS>>>(raw_gamma, raw_lambd, values,
                                            rewards, dones, out);
}